// round 1
// baseline (speedup 1.0000x reference)
#include <cuda_runtime.h>
#include <math_constants.h>

#define N_PRED 20
#define N_LAB  12

__global__ __launch_bounds__(256)
void myloss_kernel(const float4* __restrict__ pred,   // [B, 20, 4]
                   const float4* __restrict__ label,  // [B, 12, 4]
                   float* __restrict__ out, int B)
{
    int b = blockIdx.x * blockDim.x + threadIdx.x;
    if (b >= B) return;

    // Load all 20 preds into registers (contiguous 320B per row).
    float4 p[N_PRED];
    const float4* pr = pred + (long)b * N_PRED;
    #pragma unroll
    for (int j = 0; j < N_PRED; j++) p[j] = pr[j];

    const float4* lb = label + (long)b * N_LAB;

    float loss_pair = 0.f;
    unsigned mask = 0u;

    #pragma unroll
    for (int l = 0; l < N_LAB; l++) {
        float4 y = lb[l];
        float best_c = CUDART_INF_F;
        float best_p = 0.f;
        int   best_j = 0;
        // argmin over scaled cost: sqrt(d2) + |dr|  (0.5 factors are a common
        // scale -> argmin invariant; min cost recovered as 0.5*best_c, which
        // equals the reference's 0.5*mdist + 0.5*mrdiff exactly).
        #pragma unroll
        for (int j = 0; j < N_PRED; j++) {
            float dx = y.x - p[j].x;
            float dy = y.y - p[j].y;
            float c  = sqrtf(fmaf(dx, dx, dy * dy)) + fabsf(y.z - p[j].z);
            if (c < best_c) {            // strict < keeps FIRST min (jnp.argmin)
                best_c = c;
                best_j = j;
                best_p = p[j].w;
            }
        }
        loss_pair += 0.5f * best_c - __logf(best_p + 1e-6f);
        mask |= (1u << best_j);
    }

    // Unpaired term over preds not in the matched set.
    float loss_unpair = 0.f;
    #pragma unroll
    for (int j = 0; j < N_PRED; j++) {
        if (!((mask >> j) & 1u)) {
            loss_unpair += -__logf(1.0f - p[j].w + 1e-6f) + 0.5f * p[j].z;
        }
    }
    loss_unpair *= 0.5f;  // LAMBDA_UNPAIR

    out[b] = loss_pair * (1.0f / N_LAB) + loss_unpair * (1.0f / (N_PRED - N_LAB));
}

extern "C" void kernel_launch(void* const* d_in, const int* in_sizes, int n_in,
                              void* d_out, int out_size)
{
    const float4* pred  = (const float4*)d_in[0];
    const float4* label = (const float4*)d_in[1];
    float* out = (float*)d_out;
    int B = in_sizes[0] / (N_PRED * 4);

    int threads = 256;
    int blocks = (B + threads - 1) / threads;
    myloss_kernel<<<blocks, threads>>>(pred, label, out, B);
}

// round 2
// speedup vs baseline: 1.6209x; 1.6209x over previous
#include <cuda_runtime.h>
#include <math_constants.h>

#define N_PRED 20
#define N_LAB  12

__device__ __forceinline__ float sqrt_approx(float x) {
    float r; asm("sqrt.approx.f32 %0, %1;" : "=f"(r) : "f"(x)); return r;
}

__global__ __launch_bounds__(256)
void myloss_kernel(const float4* __restrict__ pred,   // [B, 20, 4]
                   const float4* __restrict__ label,  // [B, 12, 4]
                   float* __restrict__ out, int B)
{
    int b = blockIdx.x * blockDim.x + threadIdx.x;
    if (b >= B) return;

    // Preds in registers; pack index j into the low 5 mantissa bits of pw so
    // the tournament carries a single payload. Perturbs pw by <= 31 ulp
    // (~4e-6 relative) -> negligible in log(pw+1e-6).
    float px[N_PRED], py[N_PRED], pz[N_PRED], pwj[N_PRED];
    const float4* pr = pred + (long)b * N_PRED;
    #pragma unroll
    for (int j = 0; j < N_PRED; j++) {
        float4 v = pr[j];
        px[j] = v.x; py[j] = v.y; pz[j] = v.z;
        pwj[j] = __uint_as_float((__float_as_uint(v.w) & ~31u) | (unsigned)j);
    }

    const float4* lb = label + (long)b * N_LAB;
    float loss_pair = 0.f;
    unsigned mask = 0u;

    #pragma unroll
    for (int l = 0; l < N_LAB; l++) {
        float4 y = lb[l];

        // Compute costs for pairs of candidates and fuse the first tournament
        // level so only 10 (cost,payload) slots stay live.
        float cc[10], ww[10];
        #pragma unroll
        for (int h = 0; h < 10; h++) {
            int j0 = 2 * h, j1 = 2 * h + 1;
            float dx0 = y.x - px[j0], dy0 = y.y - py[j0];
            float c0 = sqrt_approx(fmaf(dx0, dx0, dy0 * dy0)) + fabsf(y.z - pz[j0]);
            float dx1 = y.x - px[j1], dy1 = y.y - py[j1];
            float c1 = sqrt_approx(fmaf(dx1, dx1, dy1 * dy1)) + fabsf(y.z - pz[j1]);
            bool lt = c1 < c0;            // strict < : earlier index wins ties
            cc[h] = lt ? c1 : c0;
            ww[h] = lt ? pwj[j1] : pwj[j0];
        }
        // Tree over 10 winners; left block has lower indices, strict < keeps
        // first occurrence -> exact jnp.argmin tie-break.
        #pragma unroll
        for (int stride = 1; stride < 10; stride *= 2) {
            #pragma unroll
            for (int h = 0; h + stride < 10; h += 2 * stride) {
                bool lt = cc[h + stride] < cc[h];
                cc[h] = lt ? cc[h + stride] : cc[h];
                ww[h] = lt ? ww[h + stride] : ww[h];
            }
        }

        unsigned ji = __float_as_uint(ww[0]) & 31u;
        mask |= 1u << ji;
        // best cost = 0.5*(dist+rdiff) == LAMBDA_POS*mdist + LAMBDA_RAD*mrdiff
        loss_pair += 0.5f * cc[0] - __logf(ww[0] + 1e-6f);
    }

    // Unpaired preds.
    float lu = 0.f;
    #pragma unroll
    for (int j = 0; j < N_PRED; j++) {
        if (!((mask >> j) & 1u))
            lu += -__logf(1.0f - pwj[j] + 1e-6f) + 0.5f * pz[j];
    }

    out[b] = loss_pair * (1.0f / N_LAB) + lu * 0.5f * (1.0f / (N_PRED - N_LAB));
}

extern "C" void kernel_launch(void* const* d_in, const int* in_sizes, int n_in,
                              void* d_out, int out_size)
{
    const float4* pred  = (const float4*)d_in[0];
    const float4* label = (const float4*)d_in[1];
    float* out = (float*)d_out;
    int B = in_sizes[0] / (N_PRED * 4);

    int threads = 256;
    int blocks = (B + threads - 1) / threads;
    myloss_kernel<<<blocks, threads>>>(pred, label, out, B);
}

// round 3
// speedup vs baseline: 1.8792x; 1.1593x over previous
#include <cuda_runtime.h>
#include <math_constants.h>

#define N_PRED 20
#define N_LAB  12
#define HALF   10   // preds per thread

__device__ __forceinline__ float sqrt_approx(float x) {
    float r; asm("sqrt.approx.f32 %0, %1;" : "=f"(r) : "f"(x)); return r;
}

__global__ __launch_bounds__(256, 3)
void myloss_kernel(const float4* __restrict__ pred,   // [B, 20, 4]
                   const float4* __restrict__ label,  // [B, 12, 4]
                   float* __restrict__ out, int B)
{
    int t = blockIdx.x * blockDim.x + threadIdx.x;
    int b = t >> 1;          // row
    int h = t & 1;           // which half of the preds this thread owns
    if (b >= B) return;

    // This thread's 10 preds; global index packed into low 5 mantissa bits of
    // pw (<=31 ulp perturbation, ~4e-6 relative -> negligible in log(pw+eps)).
    float px[HALF], py[HALF], pz[HALF], pwj[HALF];
    const float4* pr = pred + (long)b * N_PRED + h * HALF;
    #pragma unroll
    for (int j = 0; j < HALF; j++) {
        float4 v = pr[j];
        px[j] = v.x; py[j] = v.y; pz[j] = v.z;
        pwj[j] = __uint_as_float((__float_as_uint(v.w) & ~31u) | (unsigned)(h * HALF + j));
    }

    const float4* lb = label + (long)b * N_LAB;
    float loss_pair = 0.f;
    unsigned mask = 0u;          // local mask over this thread's 10 preds

    #pragma unroll
    for (int l = 0; l < N_LAB; l++) {
        float4 y = lb[l];        // pair lanes hit same sector -> L1 broadcast

        // 10 costs, first tournament level fused (5 winners).
        float cc[5], ww[5];
        #pragma unroll
        for (int q = 0; q < 5; q++) {
            int j0 = 2 * q, j1 = 2 * q + 1;
            float dx0 = y.x - px[j0], dy0 = y.y - py[j0];
            float c0 = sqrt_approx(fmaf(dx0, dx0, dy0 * dy0)) + fabsf(y.z - pz[j0]);
            float dx1 = y.x - px[j1], dy1 = y.y - py[j1];
            float c1 = sqrt_approx(fmaf(dx1, dx1, dy1 * dy1)) + fabsf(y.z - pz[j1]);
            bool lt = c1 < c0;   // strict < : earlier index wins ties
            cc[q] = lt ? c1 : c0;
            ww[q] = lt ? pwj[j1] : pwj[j0];
        }
        // 5 -> 1 (left block always lower indices; strict < keeps first-min).
        bool lt1 = cc[1] < cc[0];
        float ca = lt1 ? cc[1] : cc[0];  float wa = lt1 ? ww[1] : ww[0];
        bool lt2 = cc[3] < cc[2];
        float cb = lt2 ? cc[3] : cc[2];  float wb = lt2 ? ww[3] : ww[2];
        bool lt3 = cb < ca;
        ca = lt3 ? cb : ca;              wa = lt3 ? wb : wa;
        bool lt4 = cc[4] < ca;
        ca = lt4 ? cc[4] : ca;           wa = lt4 ? ww[4] : wa;

        // Cross-thread merge of the two half-winners (exact first-min:
        // lexicographic on (cost, global index)).
        float oc = __shfl_xor_sync(0xffffffffu, ca, 1);
        float ow = __shfl_xor_sync(0xffffffffu, wa, 1);
        unsigned ia = __float_as_uint(wa) & 31u;
        unsigned io = __float_as_uint(ow) & 31u;
        bool take_o = (oc < ca) || (oc == ca && io < ia);
        float wc  = take_o ? oc : ca;
        float wwn = take_o ? ow : wa;
        unsigned wi = take_o ? io : ia;

        // Set mask bit if the winner is one of mine.
        unsigned lo = (unsigned)(h * HALF);
        if (wi - lo < HALF) mask |= 1u << (wi - lo);

        loss_pair += 0.5f * wc - __logf(wwn + 1e-6f);
    }

    // Unpair over my 10 preds.
    float lu = 0.f;
    #pragma unroll
    for (int j = 0; j < HALF; j++) {
        if (!((mask >> j) & 1u))
            lu += -__logf(1.0f - pwj[j] + 1e-6f) + 0.5f * pz[j];
    }
    lu += __shfl_xor_sync(0xffffffffu, lu, 1);   // partner's half

    if (h == 0)
        out[b] = loss_pair * (1.0f / N_LAB) + lu * 0.5f * (1.0f / (N_PRED - N_LAB));
}

extern "C" void kernel_launch(void* const* d_in, const int* in_sizes, int n_in,
                              void* d_out, int out_size)
{
    const float4* pred  = (const float4*)d_in[0];
    const float4* label = (const float4*)d_in[1];
    float* out = (float*)d_out;
    int B = in_sizes[0] / (N_PRED * 4);

    long threads_total = 2L * B;
    int threads = 256;
    int blocks = (int)((threads_total + threads - 1) / threads);
    myloss_kernel<<<blocks, threads>>>(pred, label, out, B);
}